// round 17
// baseline (speedup 1.0000x reference)
#include <cuda_runtime.h>
#include <cuda_bf16.h>

#define BATCH 16
#define NPTS  2048
#define CH    128
#define MROWS (BATCH * NPTS)   // 32768
#define KNN_K 7                // neighbors excluding self

#define ALPHA_C ((float)(8.0 / 9.0))
#define IA8_C   ((float)((1.0 - 8.0 / 9.0) / 8.0))
#define QRANGE  32512.0f

// ---------------- scratch (device globals; no allocation allowed) ----------
__device__ float g_pts[(size_t)MROWS * CH];
__device__ float g_Hg [(size_t)MROWS * CH];
__device__ int   g_nbr[(size_t)MROWS * KNN_K];
__device__ float g_UV [(size_t)MROWS * 12];
__device__ float g_sx [(size_t)MROWS];
__device__ signed char g_Xh[(size_t)MROWS * CH];
__device__ signed char g_Xl[(size_t)MROWS * CH];
__device__ signed char g_Rh[(size_t)MROWS * CH];
__device__ signed char g_Rl[(size_t)MROWS * CH];
__device__ signed char g_Wc_h[4 * CH * CH];
__device__ signed char g_Wc_l[4 * CH * CH];
__device__ signed char g_Wg_h[4 * CH * CH];
__device__ signed char g_Wg_l[4 * CH * CH];
__device__ float g_swc[4 * CH];
__device__ float g_swg[4 * CH];

// ---------------- helpers ---------------------------------------------------
__device__ __forceinline__ unsigned smem_u32(const void* p) {
    unsigned a;
    asm("{ .reg .u64 t; cvta.to.shared.u64 t, %1; cvt.u32.u64 %0, t; }"
        : "=r"(a) : "l"(p));
    return a;
}

__device__ __forceinline__ void ldsm_x4(unsigned addr, unsigned& r0, unsigned& r1,
                                        unsigned& r2, unsigned& r3) {
    asm volatile("ldmatrix.sync.aligned.m8n8.x4.shared.b16 {%0,%1,%2,%3}, [%4];"
                 : "=r"(r0), "=r"(r1), "=r"(r2), "=r"(r3) : "r"(addr));
}

__device__ __forceinline__ void imma_s8(int* c, const unsigned* a,
                                        unsigned b0, unsigned b1) {
    asm volatile(
        "mma.sync.aligned.m16n8k32.row.col.s32.s8.s8.s32 "
        "{%0,%1,%2,%3}, {%4,%5,%6,%7}, {%8,%9}, {%0,%1,%2,%3};"
        : "+r"(c[0]), "+r"(c[1]), "+r"(c[2]), "+r"(c[3])
        : "r"(a[0]), "r"(a[1]), "r"(a[2]), "r"(a[3]), "r"(b0), "r"(b1));
}

__device__ __forceinline__ void cp16(unsigned saddr, const void* gptr) {
    asm volatile("cp.async.cg.shared.global [%0], [%1], 16;"
                 :: "r"(saddr), "l"(gptr) : "memory");
}
#define CP_COMMIT() asm volatile("cp.async.commit_group;" ::: "memory")
#define CP_WAIT0()  asm volatile("cp.async.wait_group 0;" ::: "memory")
#define CP_WAIT1()  asm volatile("cp.async.wait_group 1;" ::: "memory")

// int8 tile: 128 rows x 128 bytes, 8x16B granules/row, XOR swizzle by row&7.
__device__ __forceinline__ unsigned tile_addr_i8(unsigned base, int rbase,
                                                 int kb, int lane) {
    int r  = rbase + (lane & 7) + ((lane >> 3) & 1) * 8;
    int cb = kb + (lane >> 4) * 16;
    int g  = ((cb >> 4) ^ (r & 7)) & 7;
    return base + (unsigned)r * 128u + (unsigned)g * 16u;
}

// async-stage one 128x128 int8 tile into swizzled smem (512 threads)
__device__ __forceinline__ void stage_tile_i8(unsigned sdst,
                                              const signed char* gsrc, int tid) {
    #pragma unroll
    for (int it = 0; it < 2; it++) {
        int idx = it * 512 + tid;          // [0, 1024) 16B granules
        int row = idx >> 3;
        int g   = idx & 7;
        unsigned off = (unsigned)row * 128u + (unsigned)(((g ^ (row & 7)) & 7) * 16);
        cp16(sdst + off, gsrc + (size_t)row * 128 + g * 16);
    }
}

__device__ __forceinline__ unsigned pack4(int b0, int b1, int b2, int b3) {
    return (b0 & 0xFF) | ((b1 & 0xFF) << 8) | ((b2 & 0xFF) << 16) | ((b3 & 0xFF) << 24);
}

// quantize v -> int16 q, split to hi/lo bytes; relu variant shares the scale
__device__ __forceinline__ void q16(float v, float inv, int& h, int& l,
                                    int& rh, int& rl) {
    int q = __float2int_rn(v * inv);
    h = (q + 128) >> 8;
    l = q - (h << 8);
    int qr = max(q, 0);
    rh = (qr + 128) >> 8;
    rl = qr - (rh << 8);
}

// warp-wide max (32 lanes)
__device__ __forceinline__ float warp_max(float m) {
    #pragma unroll
    for (int s = 16; s > 0; s >>= 1)
        m = fmaxf(m, __shfl_xor_sync(0xffffffffu, m, s));
    return m;
}

// quantize a 4-value slice of a row + store to the 4 planes
__device__ __forceinline__ void quant_store_row(float4 p, int row, int lane) {
    float m = fmaxf(fmaxf(fabsf(p.x), fabsf(p.y)), fmaxf(fabsf(p.z), fabsf(p.w)));
    m = warp_max(m);
    float mx  = fmaxf(m, 1e-20f);
    float inv = QRANGE / mx;
    int h0, l0, rh0, rl0, h1, l1, rh1, rl1, h2, l2, rh2, rl2, h3, l3, rh3, rl3;
    q16(p.x, inv, h0, l0, rh0, rl0);
    q16(p.y, inv, h1, l1, rh1, rl1);
    q16(p.z, inv, h2, l2, rh2, rl2);
    q16(p.w, inv, h3, l3, rh3, rl3);
    size_t off = (size_t)row * CH + lane * 4;
    *(unsigned*)(g_Xh + off) = pack4(h0, h1, h2, h3);
    *(unsigned*)(g_Xl + off) = pack4(l0, l1, l2, l3);
    *(unsigned*)(g_Rh + off) = pack4(rh0, rh1, rh2, rh3);
    *(unsigned*)(g_Rl + off) = pack4(rl0, rl1, rl2, rl3);
    if (lane == 0) g_sx[row] = mx / QRANGE;
}

// ---------------- transpose (B,C,N) -> (B,N,C) -----------------------------
__global__ __launch_bounds__(256) void transpose_in_kernel(const float* __restrict__ src)
{
    __shared__ float tile[32][33];
    int b  = blockIdx.z;
    int c0 = blockIdx.y * 32;
    int n0 = blockIdx.x * 32;
    int tx = threadIdx.x, ty = threadIdx.y;
    #pragma unroll
    for (int r = ty; r < 32; r += 8)
        tile[r][tx] = src[((size_t)b * CH + c0 + r) * NPTS + n0 + tx];
    __syncthreads();
    #pragma unroll
    for (int r = ty; r < 32; r += 8)
        g_pts[((size_t)b * NPTS + n0 + r) * CH + c0 + tx] = tile[tx][r];
}

// ---------------- transpose (B,N,C) -> (B,C,N) into output -----------------
__global__ __launch_bounds__(256) void transpose_out_kernel(float* __restrict__ dst)
{
    __shared__ float tile[32][33];
    int b  = blockIdx.z;
    int c0 = blockIdx.y * 32;
    int n0 = blockIdx.x * 32;
    int tx = threadIdx.x, ty = threadIdx.y;
    #pragma unroll
    for (int r = ty; r < 32; r += 8)
        tile[r][tx] = g_pts[((size_t)b * NPTS + n0 + r) * CH + c0 + tx];
    __syncthreads();
    #pragma unroll
    for (int r = ty; r < 32; r += 8)
        dst[((size_t)b * CH + c0 + r) * NPTS + n0 + tx] = tile[tx][r];
}

// ---------------- quant0: g_pts rows -> int8 planes (iteration 0) ----------
__global__ __launch_bounds__(256) void quant0_kernel()
{
    int row  = blockIdx.x * 8 + (threadIdx.x >> 5);
    int lane = threadIdx.x & 31;
    float4 p = *(const float4*)(g_pts + (size_t)row * CH + lane * 4);
    quant_store_row(p, row, lane);
}

// ---------------- wquant: fp32 W -> int8 hi/lo planes + per-row scales -----
__global__ __launch_bounds__(256) void wquant_kernel(const float* __restrict__ Wc,
                                                     const float* __restrict__ Wg)
{
    int id   = blockIdx.x * 8 + (threadIdx.x >> 5);   // [0, 1024)
    int lane = threadIdx.x & 31;
    bool isC = (id < 512);
    int r    = isC ? id : id - 512;                   // [0, 512): iter*128 + d
    const float* src = (isC ? Wc : Wg) + (size_t)r * CH + lane * 4;
    float4 w = *(const float4*)src;
    float m = fmaxf(fmaxf(fabsf(w.x), fabsf(w.y)), fmaxf(fabsf(w.z), fabsf(w.w)));
    m = warp_max(m);
    float mx  = fmaxf(m, 1e-20f);
    float inv = QRANGE / mx;
    int h0, l0, d0, d1, h1, l1, h2, l2, h3, l3;
    q16(w.x, inv, h0, l0, d0, d1);
    q16(w.y, inv, h1, l1, d0, d1);
    q16(w.z, inv, h2, l2, d0, d1);
    q16(w.w, inv, h3, l3, d0, d1);
    size_t off = (size_t)r * CH + lane * 4;
    if (isC) {
        *(unsigned*)(g_Wc_h + off) = pack4(h0, h1, h2, h3);
        *(unsigned*)(g_Wc_l + off) = pack4(l0, l1, l2, l3);
        if (lane == 0) g_swc[r] = mx / QRANGE;
    } else {
        *(unsigned*)(g_Wg_h + off) = pack4(h0, h1, h2, h3);
        *(unsigned*)(g_Wg_l + off) = pack4(l0, l1, l2, l3);
        if (lane == 0) g_swg[r] = mx / QRANGE;
    }
}

// ---------------- KNN: 7 nearest neighbors (excluding self) ----------------
__global__ __launch_bounds__(128) void knn_kernel(const float* __restrict__ xyz)
{
    __shared__ float sx[NPTS], sy[NPTS], sz[NPTS], s2[NPTS];
    int b = blockIdx.y;
    const float* base = xyz + (size_t)b * 3 * NPTS;
    for (int j = threadIdx.x; j < NPTS; j += 128) {
        float x = base[j], y = base[NPTS + j], z = base[2 * NPTS + j];
        sx[j] = x; sy[j] = y; sz[j] = z;
        s2[j] = x * x + y * y + z * z;
    }
    __syncthreads();

    int i = blockIdx.x * 128 + threadIdx.x;
    float xi = sx[i], yi = sy[i], zi = sz[i], x2i = s2[i];

    float d[8];
    int   id[8];
    #pragma unroll
    for (int t = 0; t < 8; t++) { d[t] = 3.0e38f; id[t] = 0; }

    for (int j = 0; j < NPTS; j++) {
        float inner = xi * sx[j] + yi * sy[j] + zi * sz[j];
        float dist  = x2i + s2[j] - 2.0f * inner;
        if (dist < d[7]) {
            #pragma unroll
            for (int s = 7; s >= 1; --s) {
                if      (dist < d[s - 1]) { d[s] = d[s - 1]; id[s] = id[s - 1]; }
                else if (dist < d[s])     { d[s] = dist;     id[s] = j; }
            }
            if (dist < d[0]) { d[0] = dist; id[0] = j; }
        }
    }
    int* out = g_nbr + (size_t)(b * NPTS + i) * KNN_K;
    #pragma unroll
    for (int t = 0; t < KNN_K; t++) out[t] = id[t + 1];
}

// ---------------- int8 IMMA GEMM, persistent + pipelined -------------------
// y=0: Hc = relu(X)@Wc^T -> g_pts += (8/9)*Hc (in place)  [planes g_Rh/g_Rl]
// y=1: Hg = X@Wg^T       -> g_Hg                          [planes g_Xh/g_Xl]
// D = s_x[m]*s_w[n]*(65536*acc1 + 256*acc2); acc1 = h*h, acc2 = h*l + l*h.
// Grid (74, 2): 1 CTA/SM persistent. 16 warps 4(M)x4(N), warp tile 32x32.
#define GRID_X   74
#define NTILES   (MROWS / 128)   // 256
#define GI_B_H   0
#define GI_B_L   16384
#define GI_A(st) (32768 + (st) * 32768)   // hi at +0, lo at +16384
#define GEMM_SMEM (32768 + 2 * 32768)     // 98304

__global__ __launch_bounds__(512, 1) void gemm_i8_kernel(int iter)
{
    extern __shared__ __align__(1024) unsigned char smem[];
    unsigned sbase = smem_u32(smem);
    int tid  = threadIdx.x;
    int lane = tid & 31;
    int wid  = tid >> 5;
    int mw   = wid & 3;    // M warp (0-3)
    int nw   = wid >> 2;   // N warp (0-3)
    bool reluPath = (blockIdx.y == 0);

    const signed char* __restrict__ Ah = reluPath ? g_Rh : g_Xh;
    const signed char* __restrict__ Al = reluPath ? g_Rl : g_Xl;
    const signed char* __restrict__ Wh = (reluPath ? g_Wc_h : g_Wg_h) + (size_t)iter * CH * CH;
    const signed char* __restrict__ Wl = (reluPath ? g_Wc_l : g_Wg_l) + (size_t)iter * CH * CH;
    const float* __restrict__ sw = (reluPath ? g_swc : g_swg) + iter * CH;

    // per-lane column scales (fixed across tiles)
    float swv[4][2];
    #pragma unroll
    for (int nt = 0; nt < 4; nt++) {
        int c = nw * 32 + nt * 8 + (lane & 3) * 2;
        swv[nt][0] = __ldg(&sw[c]);
        swv[nt][1] = __ldg(&sw[c + 1]);
    }

    int t0 = blockIdx.x;
    stage_tile_i8(sbase + GI_B_H, Wh, tid);
    stage_tile_i8(sbase + GI_B_L, Wl, tid);
    stage_tile_i8(sbase + GI_A(0),         Ah + (size_t)t0 * 128 * CH, tid);
    stage_tile_i8(sbase + GI_A(0) + 16384, Al + (size_t)t0 * 128 * CH, tid);
    CP_COMMIT();

    int buf = 0;
    for (int t = t0; t < NTILES; t += GRID_X, buf ^= 1) {
        int tn = t + GRID_X;
        if (tn < NTILES) {
            stage_tile_i8(sbase + GI_A(buf ^ 1),         Ah + (size_t)tn * 128 * CH, tid);
            stage_tile_i8(sbase + GI_A(buf ^ 1) + 16384, Al + (size_t)tn * 128 * CH, tid);
            CP_COMMIT();
            CP_WAIT1();
        } else {
            CP_WAIT0();
        }
        __syncthreads();

        unsigned abh = sbase + GI_A(buf);
        unsigned abl = abh + 16384;
        int m0 = t * 128;

        int acc1[2][4][4], acc2[2][4][4];
        #pragma unroll
        for (int mt = 0; mt < 2; mt++)
            #pragma unroll
            for (int nt = 0; nt < 4; nt++)
                #pragma unroll
                for (int e = 0; e < 4; e++) { acc1[mt][nt][e] = 0; acc2[mt][nt][e] = 0; }

        #pragma unroll
        for (int kk = 0; kk < 4; kk++) {
            int kb = kk * 32;
            unsigned ah[2][4], al[2][4];
            #pragma unroll
            for (int mt = 0; mt < 2; mt++) {
                int rb = mw * 32 + mt * 16;
                ldsm_x4(tile_addr_i8(abh, rb, kb, lane),
                        ah[mt][0], ah[mt][1], ah[mt][2], ah[mt][3]);
                ldsm_x4(tile_addr_i8(abl, rb, kb, lane),
                        al[mt][0], al[mt][1], al[mt][2], al[mt][3]);
            }
            unsigned bh[2][4], bl[2][4];
            #pragma unroll
            for (int pp = 0; pp < 2; pp++) {
                int nb = nw * 32 + pp * 16;
                ldsm_x4(tile_addr_i8(sbase + GI_B_H, nb, kb, lane),
                        bh[pp][0], bh[pp][1], bh[pp][2], bh[pp][3]);
                ldsm_x4(tile_addr_i8(sbase + GI_B_L, nb, kb, lane),
                        bl[pp][0], bl[pp][1], bl[pp][2], bl[pp][3]);
            }
            #pragma unroll
            for (int mt = 0; mt < 2; mt++) {
                #pragma unroll
                for (int nt = 0; nt < 4; nt++) {
                    int pp = nt >> 1, h = nt & 1;
                    imma_s8(acc1[mt][nt], ah[mt], bh[pp][h], bh[pp][h + 2]);
                    imma_s8(acc2[mt][nt], ah[mt], bl[pp][h], bl[pp][h + 2]);
                    imma_s8(acc2[mt][nt], al[mt], bh[pp][h], bh[pp][h + 2]);
                }
            }
        }

        // Epilogue: f = sx*sw*(65536*acc1 + 256*acc2)
        #pragma unroll
        for (int mt = 0; mt < 2; mt++) {
            int r0 = m0 + mw * 32 + mt * 16 + (lane >> 2);
            float sx0 = __ldg(&g_sx[r0]);
            float sx1 = __ldg(&g_sx[r0 + 8]);
            #pragma unroll
            for (int nt = 0; nt < 4; nt++) {
                int c = nw * 32 + nt * 8 + (lane & 3) * 2;
                float f0 = fmaf(65536.0f, (float)acc1[mt][nt][0],
                                256.0f * (float)acc2[mt][nt][0]) * (sx0 * swv[nt][0]);
                float f1 = fmaf(65536.0f, (float)acc1[mt][nt][1],
                                256.0f * (float)acc2[mt][nt][1]) * (sx0 * swv[nt][1]);
                float f2 = fmaf(65536.0f, (float)acc1[mt][nt][2],
                                256.0f * (float)acc2[mt][nt][2]) * (sx1 * swv[nt][0]);
                float f3 = fmaf(65536.0f, (float)acc1[mt][nt][3],
                                256.0f * (float)acc2[mt][nt][3]) * (sx1 * swv[nt][1]);
                if (reluPath) {
                    float* p0 = g_pts + (size_t)r0 * CH + c;
                    float* p1 = p0 + 8 * CH;
                    float2 v0 = *(float2*)p0, v1 = *(float2*)p1;
                    v0.x += ALPHA_C * f0; v0.y += ALPHA_C * f1;
                    v1.x += ALPHA_C * f2; v1.y += ALPHA_C * f3;
                    *(float2*)p0 = v0;
                    *(float2*)p1 = v1;
                } else {
                    float* q0 = g_Hg + (size_t)r0 * CH + c;
                    float* q1 = q0 + 8 * CH;
                    *(float2*)q0 = make_float2(f0, f1);
                    *(float2*)q1 = make_float2(f2, f3);
                }
            }
        }
        __syncthreads();
    }
}

// ---------------- combine: pts += IA8*(Hg self + 7 nbrs); emit int8 planes -
__global__ __launch_bounds__(256) void combine_kernel(int emit)
{
    int row  = blockIdx.x * 8 + (threadIdx.x >> 5);
    int lane = threadIdx.x & 31;
    int bbase = row & ~(NPTS - 1);

    const int* nb = g_nbr + (size_t)row * KNN_K;
    int j[KNN_K];
    #pragma unroll
    for (int t = 0; t < KNN_K; t++) j[t] = bbase + nb[t];

    size_t roff = (size_t)row * CH + lane * 4;
    float4 g = *(const float4*)(g_Hg + roff);
    #pragma unroll
    for (int t = 0; t < KNN_K; t++) {
        float4 v = *(const float4*)(g_Hg + (size_t)j[t] * CH + lane * 4);
        g.x += v.x; g.y += v.y; g.z += v.z; g.w += v.w;
    }
    float4 p = *(const float4*)(g_pts + roff);  // already has shortcut + A*Hc
    p.x += IA8_C * g.x;
    p.y += IA8_C * g.y;
    p.z += IA8_C * g.z;
    p.w += IA8_C * g.w;
    *(float4*)(g_pts + roff) = p;

    if (emit) quant_store_row(p, row, lane);
}

// ---------------- U = pts@Wuc^T, V = pts@Wug^T -----------------------------
__global__ __launch_bounds__(128) void uv_kernel(
    const float* __restrict__ Wuc, const float* __restrict__ Wug)
{
    __shared__ float w[12][128];
    int tid = threadIdx.x;
    for (int t = tid; t < 768; t += 128) w[t >> 7][t & 127]       = Wuc[t];
    for (int t = tid; t < 768; t += 128) w[6 + (t >> 7)][t & 127] = Wug[t];
    __syncthreads();

    int row  = blockIdx.x * 4 + (tid >> 5);
    int lane = tid & 31;
    float4 p = *(const float4*)(g_pts + (size_t)row * CH + lane * 4);

    float r[12];
    #pragma unroll
    for (int o = 0; o < 12; o++) {
        float4 wv = *(const float4*)&w[o][lane * 4];
        r[o] = p.x * wv.x + p.y * wv.y + p.z * wv.z + p.w * wv.w;
    }
    #pragma unroll
    for (int o = 0; o < 12; o++) {
        #pragma unroll
        for (int s = 16; s > 0; s >>= 1)
            r[o] += __shfl_xor_sync(0xffffffff, r[o], s);
    }
    if (lane == 0) {
        float* out = g_UV + (size_t)row * 12;
        #pragma unroll
        for (int o = 0; o < 12; o++) out[o] = r[o];
    }
}

// ---------------- final: new_xyz = combine + unpool reshape ----------------
__global__ __launch_bounds__(256) void final_kernel(
    const float* __restrict__ xyz, float* __restrict__ out)
{
    int row = blockIdx.x * 256 + threadIdx.x;   // [0, 32768)
    int b = row >> 11, n = row & (NPTS - 1);
    int bbase = b << 11;

    const float* uv = g_UV + (size_t)row * 12;
    float nv[6];
    #pragma unroll
    for (int o = 0; o < 6; o++) nv[o] = uv[6 + o];

    const int* nb = g_nbr + (size_t)row * KNN_K;
    #pragma unroll
    for (int t = 0; t < KNN_K; t++) {
        const float* v = g_UV + (size_t)(bbase + nb[t]) * 12 + 6;
        #pragma unroll
        for (int o = 0; o < 6; o++) nv[o] += v[o];
    }

    #pragma unroll
    for (int c = 0; c < 3; c++) {
        float base = xyz[(size_t)b * 3 * NPTS + c * NPTS + n];
        #pragma unroll
        for (int p = 0; p < 2; p++) {
            float val = ALPHA_C * uv[2 * c + p] + IA8_C * nv[2 * c + p] + base;
            out[(size_t)b * 3 * 2 * NPTS + c * 2 * NPTS + p * NPTS + n] = val;
        }
    }
}

// ---------------------------------------------------------------------------
extern "C" void kernel_launch(void* const* d_in, const int* in_sizes, int n_in,
                              void* d_out, int out_size)
{
    const float* xyz    = (const float*)d_in[0];   // (16, 3, 2048)
    const float* points = (const float*)d_in[1];   // (16, 128, 2048)
    const float* Wc     = (const float*)d_in[2];   // (4, 128, 128)
    const float* Wg     = (const float*)d_in[3];   // (4, 128, 128)
    const float* Wuc    = (const float*)d_in[4];   // (6, 128)
    const float* Wug    = (const float*)d_in[5];   // (6, 128)
    float* out = (float*)d_out;                    // [new_xyz | pts^T]

    cudaFuncSetAttribute(gemm_i8_kernel,
                         cudaFuncAttributeMaxDynamicSharedMemorySize, GEMM_SMEM);

    dim3 tposGrid(NPTS / 32, CH / 32, BATCH);
    dim3 tposBlk(32, 8);

    transpose_in_kernel<<<tposGrid, tposBlk>>>(points);
    knn_kernel<<<dim3(NPTS / 128, BATCH), 128>>>(xyz);
    wquant_kernel<<<128, 256>>>(Wc, Wg);
    quant0_kernel<<<MROWS / 8, 256>>>();

    for (int i = 0; i < 4; i++) {
        gemm_i8_kernel<<<dim3(GRID_X, 2), 512, GEMM_SMEM>>>(i);
        combine_kernel<<<MROWS / 8, 256>>>(i < 3 ? 1 : 0);
    }

    uv_kernel<<<MROWS / 4, 128>>>(Wuc, Wug);
    final_kernel<<<MROWS / 256, 256>>>(xyz, out);
    transpose_out_kernel<<<tposGrid, tposBlk>>>(out + (size_t)BATCH * 3 * 2 * NPTS);
}